// round 15
// baseline (speedup 1.0000x reference)
#include <cuda_runtime.h>
#include <cuda_fp16.h>
#include <cstdint>

// ---------------------------------------------------------------------------
// DSConv2d: offset conv (3x3, 128->18) + deformable conv (3x3, 128->128)
// B=16, C1=C2=128, H=W=80, fp32.
// Round 15: fused kernel with PIPELINED phase 1 — per-tap A split into two
// 64-channel half-chunks, 4 half-buffers (hi x2, lo x2), build(s+1) overlaps
// MMA(s), 1 sync per half-tap. Phase 2 (deform) unchanged and validated.
// ---------------------------------------------------------------------------

#define Hh 80
#define Ww 80
#define HW 6400
#define C1 128
#define C2 128
#define BATCH 16
#define OFFC 18

static __device__ __half g_xTh[BATCH * HW * C1];        // 26.2 MB NHWC fp16 hi
static __device__ __half g_xTl[BATCH * HW * C1];        // 26.2 MB NHWC fp16 lo
static __device__ uint2  g_wF[9 * 8 * 16 * 32];         // deform B frags (fp16)
static __device__ uint4  g_oF[9 * 8 * 4 * 32];          // offset B frags (hi/lo), N=32

// ============================================================================
// common helpers
// ============================================================================
__device__ __forceinline__ uint32_t smem_u32(const void* p) {
    uint32_t a;
    asm("{ .reg .u64 t; cvta.to.shared.u64 t, %1; cvt.u32.u64 %0, t; }"
        : "=r"(a) : "l"(p));
    return a;
}

__device__ __forceinline__ void ldsm_x4(uint32_t* r, uint32_t saddr) {
    asm volatile("ldmatrix.sync.aligned.m8n8.x4.shared.b16 {%0,%1,%2,%3}, [%4];"
                 : "=r"(r[0]), "=r"(r[1]), "=r"(r[2]), "=r"(r[3])
                 : "r"(saddr));
}

__device__ __forceinline__ void mma16816h(float* d, const uint32_t* a,
                                          const uint32_t* b) {
    asm volatile(
        "mma.sync.aligned.m16n8k16.row.col.f32.f16.f16.f32 "
        "{%0,%1,%2,%3}, {%4,%5,%6,%7}, {%8,%9}, {%0,%1,%2,%3};"
        : "+f"(d[0]), "+f"(d[1]), "+f"(d[2]), "+f"(d[3])
        : "r"(a[0]), "r"(a[1]), "r"(a[2]), "r"(a[3]),
          "r"(b[0]), "r"(b[1]));
}

__device__ __forceinline__ uint32_t hsplit2(float va, float vb, uint32_t& lo) {
    __half ha = __float2half_rn(va);
    __half hb = __float2half_rn(vb);
    __half la = __float2half_rn(va - __half2float(ha));
    __half lb = __float2half_rn(vb - __half2float(hb));
    lo = ((uint32_t)__half_as_ushort(lb) << 16) | (uint32_t)__half_as_ushort(la);
    return ((uint32_t)__half_as_ushort(hb) << 16) | (uint32_t)__half_as_ushort(ha);
}

// ============================================================================
// Kernel 0a: NCHW -> NHWC fp16 hi/lo planes
// ============================================================================
__global__ __launch_bounds__(256) void nhwc_kernel(const float* __restrict__ x)
{
    __shared__ float tile[128][81];
    const int h = blockIdx.x;
    const int b = blockIdx.y;
    const int t = threadIdx.x;

    for (int idx = t; idx < 128 * 80; idx += 256) {
        int c = idx / 80;
        int w = idx - c * 80;
        tile[c][w] = x[((size_t)(b * C1 + c) * Hh + h) * Ww + w];
    }
    __syncthreads();
    for (int idx = t; idx < 80 * 128; idx += 256) {
        int w = idx >> 7;
        int c = idx & 127;
        float v = tile[c][w];
        __half hi = __float2half_rn(v);
        __half lo = __float2half_rn(v - __half2float(hi));
        size_t o = ((size_t)b * HW + h * Ww + w) * C1 + c;
        g_xTh[o] = hi;
        g_xTl[o] = lo;
    }
}

// ============================================================================
// Kernel 0b: deform weights -> m16n8k16 B frags, fp16 single-term
// ============================================================================
__global__ __launch_bounds__(256) void prep_wfrag_kernel(const float* __restrict__ wgt)
{
    int i = blockIdx.x * 256 + threadIdx.x;
    if (i >= 9 * 8 * 16 * 32) return;
    int lane = i & 31;
    int nf   = (i >> 5) & 15;
    int kc   = (i >> 9) & 7;
    int tap  = i >> 12;
    int n  = nf * 8 + (lane >> 2);
    int kb = kc * 16 + (lane & 3) * 2;

    __half h00 = __float2half_rn(wgt[(n * 128 + kb + 0) * 9 + tap]);
    __half h01 = __float2half_rn(wgt[(n * 128 + kb + 1) * 9 + tap]);
    __half h10 = __float2half_rn(wgt[(n * 128 + kb + 8) * 9 + tap]);
    __half h11 = __float2half_rn(wgt[(n * 128 + kb + 9) * 9 + tap]);

    uint2 v;
    v.x = ((uint32_t)__half_as_ushort(h01) << 16) | (uint32_t)__half_as_ushort(h00);
    v.y = ((uint32_t)__half_as_ushort(h11) << 16) | (uint32_t)__half_as_ushort(h10);
    g_wF[i] = v;
}

// ============================================================================
// Kernel 0c: offset weights -> B frags, fp16 hi/lo, N pad 18->32
// ============================================================================
__global__ __launch_bounds__(256) void prep_ofrag_kernel(const float* __restrict__ ow)
{
    int i = blockIdx.x * 256 + threadIdx.x;
    if (i >= 9 * 8 * 4 * 32) return;
    int lane = i & 31;
    int nf   = (i >> 5) & 3;
    int kc   = (i >> 7) & 7;
    int tap  = i >> 10;
    int n  = nf * 8 + (lane >> 2);
    int kb = kc * 16 + (lane & 3) * 2;

    float w00 = 0.f, w01 = 0.f, w10 = 0.f, w11 = 0.f;
    if (n < OFFC) {
        w00 = ow[(n * 128 + kb + 0) * 9 + tap];
        w01 = ow[(n * 128 + kb + 1) * 9 + tap];
        w10 = ow[(n * 128 + kb + 8) * 9 + tap];
        w11 = ow[(n * 128 + kb + 9) * 9 + tap];
    }
    uint4 v;
    uint32_t l01, l89;
    v.x = hsplit2(w00, w01, l01);
    v.y = hsplit2(w10, w11, l89);
    v.z = l01;
    v.w = l89;
    g_oF[i] = v;
}

// ============================================================================
// FUSED kernel: 64 px x 128 oc per block, 256 threads, 3 CTAs/SM.
// Phase 1 (offsets): per-tap A split into two 64-ch halves; 4 half-buffers
//   (hi[2], lo[2], LDA=72); pipelined build(s+1) || MMA(s), 1 sync/half-tap.
// Phase 2 (deform): validated pipelined bilinear-gather GEMM, meta from smem.
// ============================================================================
#define MPX 64
#define LDA 136          // phase-2 full-width tile (halves)
#define LDAH 72          // phase-1 half-width tile (halves), 144B rows
#define LDO 132
#define ABYTES (MPX * LDA * 2)            // 17408 (phase-2 tile)
#define HB     (MPX * LDAH * 2)           // 9216  (phase-1 half tile)

#define SM_BIAS 0
#define SM_OB   512
#define SM_OFF  640                        // 64 x 20 floats = 5120
#define SM_BUFS 5888
// phase 1: hi[j] at SM_BUFS + j*HB, lo[j] at SM_BUFS + 2*HB + j*HB
// phase 2: buf[j] at SM_BUFS + j*ABYTES  (34816 <= 4*HB = 36864)
#define SMEM_TOTAL_F (SM_BUFS + 4 * HB)    // 42752

__global__ __launch_bounds__(256, 3)
void fused_dsconv_kernel(const float* __restrict__ ob,
                         const float* __restrict__ bias,
                         float* __restrict__ out)
{
    extern __shared__ char smem[];
    const uint32_t sb = smem_u32(smem);
    float* s_bias = reinterpret_cast<float*>(smem + SM_BIAS);
    float* s_ob   = reinterpret_cast<float*>(smem + SM_OB);
    float* s_off  = reinterpret_cast<float*>(smem + SM_OFF);
    float* s_out  = reinterpret_cast<float*>(smem + SM_BUFS);  // reuse post-MMA

    const int t    = threadIdx.x;
    const int wid  = t >> 5;
    const int lane = t & 31;
    const int b    = blockIdx.y;
    const int pix0 = blockIdx.x * MPX;

    const __half* xh = g_xTh + (size_t)b * HW * C1;
    const __half* xl = g_xTl + (size_t)b * HW * C1;

    if (t < 128) s_bias[t] = bias[t];
    if (t < OFFC) s_ob[t] = ob[t];

    // ldmatrix lane addressing (shared by both phases)
    const int tile = lane >> 3;
    const int rr   = ((tile & 1) << 3) + (lane & 7);
    const int cbm  = (tile >> 1) << 3;

    // =========================== PHASE 1: offsets ===========================
    {
        const int wm = wid & 3;    // 4 m-frags of 16 px
        const int wn = wid >> 2;   // 2 n-groups (2 nfrags = 16 oc each)
        const int m0 = wm * 16;

        float oacc[2][4];
#pragma unroll
        for (int j = 0; j < 2; j++)
#pragma unroll
            for (int r = 0; r < 4; r++) oacc[j][r] = 0.f;

        // build half-chunk s into half-buffer slot j (hi+lo)
        auto build_half = [&](int s, int j) {
            const int tap = s >> 1;
            const int cb0 = (s & 1) * 64;
            __half* Ah = reinterpret_cast<__half*>(smem + SM_BUFS + j * HB);
            __half* Al = reinterpret_cast<__half*>(smem + SM_BUFS + 2 * HB + j * HB);
            const int ki = tap / 3;
            const int kj = tap % 3;
            const int pxbase = wid * 8;
#pragma unroll 2
            for (int i = 0; i < 8; i++) {
                const int px  = pxbase + i;
                const int pix = pix0 + px;
                const int ho  = pix / Ww;
                const int wo  = pix - ho * Ww;
                const int sy  = ho - 1 + ki;
                const int sx  = wo - 1 + kj;
                uint32_t vh = 0u, vl = 0u;
                if (sy >= 0 && sy < Hh && sx >= 0 && sx < Ww) {
                    const size_t ro = (size_t)(sy * Ww + sx) * C1 + cb0;
                    vh = *(reinterpret_cast<const uint32_t*>(xh + ro) + lane);
                    vl = *(reinterpret_cast<const uint32_t*>(xl + ro) + lane);
                }
                *reinterpret_cast<uint32_t*>(Ah + px * LDAH + lane * 2) = vh;
                *reinterpret_cast<uint32_t*>(Al + px * LDAH + lane * 2) = vl;
            }
        };

        build_half(0, 0);
        __syncthreads();

#pragma unroll 1
        for (int s = 0; s < 18; s++) {
            const int j = s & 1;
            if (s < 17) build_half(s + 1, 1 - j);

            const int tap  = s >> 1;
            const int half = s & 1;
            const uint32_t hbase = sb + SM_BUFS + j * HB;
            const uint32_t lbase = hbase + 2 * HB;
#pragma unroll
            for (int kcl = 0; kcl < 4; kcl++) {
                const int kc = half * 4 + kcl;
                uint32_t bh[2][2], bl[2][2];
                const uint4* wf = g_oF + (((size_t)tap * 8 + kc) * 4 + wn * 2) * 32 + lane;
#pragma unroll
                for (int j2 = 0; j2 < 2; j2++) {
                    uint4 bv = wf[j2 * 32];
                    bh[j2][0] = bv.x; bh[j2][1] = bv.y;
                    bl[j2][0] = bv.z; bl[j2][1] = bv.w;
                }
                uint32_t ah[4], al[4];
                uint32_t off = ((m0 + rr) * LDAH + kcl * 16 + cbm) * 2;
                ldsm_x4(ah, hbase + off);
                ldsm_x4(al, lbase + off);
#pragma unroll
                for (int j2 = 0; j2 < 2; j2++) {
                    mma16816h(oacc[j2], ah, bh[j2]);
                    mma16816h(oacc[j2], ah, bl[j2]);
                    mma16816h(oacc[j2], al, bh[j2]);
                }
            }
            __syncthreads();
        }

        // ---- offsets (+bias) -> s_off[px][20] ----
        {
            const int r0 = lane >> 2;
            const int c0 = (lane & 3) * 2;
#pragma unroll
            for (int j = 0; j < 2; j++) {
                const int col = wn * 16 + j * 8 + c0;
                if (col < OFFC) {
                    s_off[(m0 + r0) * 20 + col]     = oacc[j][0] + s_ob[col];
                    s_off[(m0 + r0 + 8) * 20 + col] = oacc[j][2] + s_ob[col];
                }
                if (col + 1 < OFFC) {
                    s_off[(m0 + r0) * 20 + col + 1]     = oacc[j][1] + s_ob[col + 1];
                    s_off[(m0 + r0 + 8) * 20 + col + 1] = oacc[j][3] + s_ob[col + 1];
                }
            }
        }
        __syncthreads();
    }

    // =========================== PHASE 2: deform ============================
    const int wm = wid & 1;    // 2 m-groups of 32 px
    const int wn = wid >> 1;   // 4 n-groups of 32 oc

    float acc[2][4][4];
#pragma unroll
    for (int mt = 0; mt < 2; mt++)
#pragma unroll
        for (int j = 0; j < 4; j++)
#pragma unroll
            for (int r = 0; r < 4; r++) acc[mt][j][r] = 0.f;

    // per-warp register meta: lane l8 handles local px = wid*8 + l8
    const int l8  = lane & 7;
    const int pxl = wid * 8 + l8;
    const int pxm = pix0 + pxl;
    const int hom = pxm / Ww;
    const int wom = pxm - hom * Ww;
    float m_w0, m_w1, m_w2, m_w3;
    int   m_o0, m_o1, m_o2, m_o3;

    auto compute_meta = [&](int tap) {
        const int ki = tap / 3;
        const int kj = tap % 3;
        float dy = s_off[pxl * 20 + 2 * tap];
        float dx = s_off[pxl * 20 + 2 * tap + 1];
        float py  = (float)(hom - 1 + ki) + dy;
        float pxx = (float)(wom - 1 + kj) + dx;
        float y0 = floorf(py);
        float x0 = floorf(pxx);
        float wy1 = py - y0, wy0 = 1.f - wy1;
        float wx1 = pxx - x0, wx0 = 1.f - wx1;

        float yc0 = y0, yc1 = y0 + 1.f, xc0 = x0, xc1 = x0 + 1.f;
        bool vy0 = (yc0 >= 0.f) && (yc0 < (float)Hh);
        bool vy1 = (yc1 >= 0.f) && (yc1 < (float)Hh);
        bool vx0 = (xc0 >= 0.f) && (xc0 < (float)Ww);
        bool vx1 = (xc1 >= 0.f) && (xc1 < (float)Ww);
        int iy0 = (int)fminf(fmaxf(yc0, 0.f), (float)(Hh - 1));
        int iy1 = (int)fminf(fmaxf(yc1, 0.f), (float)(Hh - 1));
        int ix0 = (int)fminf(fmaxf(xc0, 0.f), (float)(Ww - 1));
        int ix1 = (int)fminf(fmaxf(xc1, 0.f), (float)(Ww - 1));
        m_w0 = (vy0 && vx0) ? wy0 * wx0 : 0.f;  m_o0 = iy0 * Ww + ix0;
        m_w1 = (vy0 && vx1) ? wy0 * wx1 : 0.f;  m_o1 = iy0 * Ww + ix1;
        m_w2 = (vy1 && vx0) ? wy1 * wx0 : 0.f;  m_o2 = iy1 * Ww + ix0;
        m_w3 = (vy1 && vx1) ? wy1 * wx1 : 0.f;  m_o3 = iy1 * Ww + ix1;
    };

    auto gather_into = [&](int bufsel) {
        __half* Ah = reinterpret_cast<__half*>(smem + SM_BUFS + bufsel * ABYTES);
        const int pxbase = wid * 8;
#pragma unroll 2
        for (int i = 0; i < 8; i++) {
            const int px = pxbase + i;
            const float w0 = __shfl_sync(0xffffffffu, m_w0, i);
            const float w1 = __shfl_sync(0xffffffffu, m_w1, i);
            const float w2 = __shfl_sync(0xffffffffu, m_w2, i);
            const float w3 = __shfl_sync(0xffffffffu, m_w3, i);
            const int o0 = __shfl_sync(0xffffffffu, m_o0, i);
            const int o1 = __shfl_sync(0xffffffffu, m_o1, i);
            const int o2 = __shfl_sync(0xffffffffu, m_o2, i);
            const int o3 = __shfl_sync(0xffffffffu, m_o3, i);
            uint2 r0 = *(reinterpret_cast<const uint2*>(xh + (size_t)o0 * C1) + lane);
            uint2 r1 = *(reinterpret_cast<const uint2*>(xh + (size_t)o1 * C1) + lane);
            uint2 r2 = *(reinterpret_cast<const uint2*>(xh + (size_t)o2 * C1) + lane);
            uint2 r3 = *(reinterpret_cast<const uint2*>(xh + (size_t)o3 * C1) + lane);
            float2 v0a = __half22float2(*reinterpret_cast<__half2*>(&r0.x));
            float2 v0b = __half22float2(*reinterpret_cast<__half2*>(&r0.y));
            float2 v1a = __half22float2(*reinterpret_cast<__half2*>(&r1.x));
            float2 v1b = __half22float2(*reinterpret_cast<__half2*>(&r1.y));
            float2 v2a = __half22float2(*reinterpret_cast<__half2*>(&r2.x));
            float2 v2b = __half22float2(*reinterpret_cast<__half2*>(&r2.y));
            float2 v3a = __half22float2(*reinterpret_cast<__half2*>(&r3.x));
            float2 v3b = __half22float2(*reinterpret_cast<__half2*>(&r3.y));
            float a0 = w0 * v0a.x; a0 = fmaf(w1, v1a.x, a0);
            a0 = fmaf(w2, v2a.x, a0); a0 = fmaf(w3, v3a.x, a0);
            float a1 = w0 * v0a.y; a1 = fmaf(w1, v1a.y, a1);
            a1 = fmaf(w2, v2a.y, a1); a1 = fmaf(w3, v3a.y, a1);
            float a2 = w0 * v0b.x; a2 = fmaf(w1, v1b.x, a2);
            a2 = fmaf(w2, v2b.x, a2); a2 = fmaf(w3, v3b.x, a2);
            float a3 = w0 * v0b.y; a3 = fmaf(w1, v1b.y, a3);
            a3 = fmaf(w2, v2b.y, a3); a3 = fmaf(w3, v3b.y, a3);
            __half2 h01 = __floats2half2_rn(a0, a1);
            __half2 h23 = __floats2half2_rn(a2, a3);
            uint2 pk;
            pk.x = *reinterpret_cast<uint32_t*>(&h01);
            pk.y = *reinterpret_cast<uint32_t*>(&h23);
            *reinterpret_cast<uint2*>(Ah + px * LDA + lane * 4) = pk;
        }
    };

    // prologue
    compute_meta(0);
    gather_into(0);
    __syncthreads();

    // pipelined main loop: 1 sync per tap
#pragma unroll 1
    for (int tap = 0; tap < 9; tap++) {
        const int cur = tap & 1;
        if (tap < 8) {
            compute_meta(tap + 1);
            gather_into(1 - cur);
        }

        const uint32_t abase = sb + SM_BUFS + cur * ABYTES;
        const int m0 = wm * 32;
#pragma unroll 1
        for (int kc = 0; kc < 8; kc++) {
            uint32_t bf[4][2];
            const uint2* wf = g_wF + (((size_t)tap * 8 + kc) * 16 + wn * 4) * 32 + lane;
#pragma unroll
            for (int j = 0; j < 4; j++) {
                uint2 bv = wf[j * 32];
                bf[j][0] = bv.x; bf[j][1] = bv.y;
            }
            uint32_t af[2][4];
#pragma unroll
            for (int mt = 0; mt < 2; mt++) {
                uint32_t off = ((m0 + mt * 16 + rr) * LDA + kc * 16 + cbm) * 2;
                ldsm_x4(af[mt], abase + off);
            }
#pragma unroll
            for (int mt = 0; mt < 2; mt++) {
#pragma unroll
                for (int j = 0; j < 4; j++) {
                    mma16816h(acc[mt][j], af[mt], bf[j]);
                }
            }
        }
        __syncthreads();
    }

    // epilogue: D frags -> smem [px][oc] -> coalesced gmem
    {
        const int r0 = lane >> 2;
        const int c0 = (lane & 3) * 2;
#pragma unroll
        for (int mt = 0; mt < 2; mt++) {
#pragma unroll
            for (int j = 0; j < 4; j++) {
                const int row = wm * 32 + mt * 16 + r0;
                const int col = wn * 32 + j * 8 + c0;
                *reinterpret_cast<float2*>(s_out + row * LDO + col) =
                    make_float2(acc[mt][j][0], acc[mt][j][1]);
                *reinterpret_cast<float2*>(s_out + (row + 8) * LDO + col) =
                    make_float2(acc[mt][j][2], acc[mt][j][3]);
            }
        }
    }
    __syncthreads();

#pragma unroll 4
    for (int j = 0; j < 32; j++) {
        int i  = t + 256 * j;   // 8192 outputs
        int oc = i >> 6;
        int px = i & 63;
        out[(size_t)(b * C2 + oc) * HW + pix0 + px] =
            s_out[px * LDO + oc] + s_bias[oc];
    }
}

// ============================================================================
// Launch: prep kernels then single fused kernel. No streams, no events.
// ============================================================================
extern "C" void kernel_launch(void* const* d_in, const int* in_sizes, int n_in,
                              void* d_out, int out_size) {
    const float* x    = (const float*)d_in[0];
    const float* ow   = (const float*)d_in[1];
    const float* ob   = (const float*)d_in[2];
    const float* wgt  = (const float*)d_in[3];
    const float* bias = (const float*)d_in[4];
    float* out = (float*)d_out;

    dim3 gn(Hh, BATCH);
    nhwc_kernel<<<gn, 256>>>(x);
    prep_wfrag_kernel<<<(9 * 8 * 16 * 32 + 255) / 256, 256>>>(wgt);
    prep_ofrag_kernel<<<(9 * 8 * 4 * 32 + 255) / 256, 256>>>(ow);

    cudaFuncSetAttribute(fused_dsconv_kernel,
                         cudaFuncAttributeMaxDynamicSharedMemorySize,
                         SMEM_TOTAL_F);
    dim3 gf(HW / MPX, BATCH);
    fused_dsconv_kernel<<<gf, 256, SMEM_TOTAL_F>>>(ob, bias, out);
}

// round 16
// speedup vs baseline: 1.0794x; 1.0794x over previous
#include <cuda_runtime.h>
#include <cuda_fp16.h>
#include <cstdint>

// ---------------------------------------------------------------------------
// DSConv2d: offset conv (3x3, 128->18) + deformable conv (3x3, 128->128)
// B=16, C1=C2=128, H=W=80, fp32.
// Round 16: r14 fused kernel + __launch_bounds__(256,4) (4 CTAs/SM, regs<=64)
// + direct-fragment epilogue (no smem s_out roundtrip).
// ---------------------------------------------------------------------------

#define Hh 80
#define Ww 80
#define HW 6400
#define C1 128
#define C2 128
#define BATCH 16
#define OFFC 18

static __device__ __half g_xTh[BATCH * HW * C1];        // 26.2 MB NHWC fp16 hi
static __device__ __half g_xTl[BATCH * HW * C1];        // 26.2 MB NHWC fp16 lo
static __device__ uint2  g_wF[9 * 8 * 16 * 32];         // deform B frags (fp16)
static __device__ uint4  g_oF[9 * 8 * 4 * 32];          // offset B frags (hi/lo), N=32

// ============================================================================
// common helpers
// ============================================================================
__device__ __forceinline__ uint32_t smem_u32(const void* p) {
    uint32_t a;
    asm("{ .reg .u64 t; cvta.to.shared.u64 t, %1; cvt.u32.u64 %0, t; }"
        : "=r"(a) : "l"(p));
    return a;
}

__device__ __forceinline__ void ldsm_x4(uint32_t* r, uint32_t saddr) {
    asm volatile("ldmatrix.sync.aligned.m8n8.x4.shared.b16 {%0,%1,%2,%3}, [%4];"
                 : "=r"(r[0]), "=r"(r[1]), "=r"(r[2]), "=r"(r[3])
                 : "r"(saddr));
}

__device__ __forceinline__ void mma16816h(float* d, const uint32_t* a,
                                          const uint32_t* b) {
    asm volatile(
        "mma.sync.aligned.m16n8k16.row.col.f32.f16.f16.f32 "
        "{%0,%1,%2,%3}, {%4,%5,%6,%7}, {%8,%9}, {%0,%1,%2,%3};"
        : "+f"(d[0]), "+f"(d[1]), "+f"(d[2]), "+f"(d[3])
        : "r"(a[0]), "r"(a[1]), "r"(a[2]), "r"(a[3]),
          "r"(b[0]), "r"(b[1]));
}

__device__ __forceinline__ uint32_t hsplit2(float va, float vb, uint32_t& lo) {
    __half ha = __float2half_rn(va);
    __half hb = __float2half_rn(vb);
    __half la = __float2half_rn(va - __half2float(ha));
    __half lb = __float2half_rn(vb - __half2float(hb));
    lo = ((uint32_t)__half_as_ushort(lb) << 16) | (uint32_t)__half_as_ushort(la);
    return ((uint32_t)__half_as_ushort(hb) << 16) | (uint32_t)__half_as_ushort(ha);
}

// ============================================================================
// Kernel 0a: NCHW -> NHWC fp16 hi/lo planes
// ============================================================================
__global__ __launch_bounds__(256) void nhwc_kernel(const float* __restrict__ x)
{
    __shared__ float tile[128][81];
    const int h = blockIdx.x;
    const int b = blockIdx.y;
    const int t = threadIdx.x;

    for (int idx = t; idx < 128 * 80; idx += 256) {
        int c = idx / 80;
        int w = idx - c * 80;
        tile[c][w] = x[((size_t)(b * C1 + c) * Hh + h) * Ww + w];
    }
    __syncthreads();
    for (int idx = t; idx < 80 * 128; idx += 256) {
        int w = idx >> 7;
        int c = idx & 127;
        float v = tile[c][w];
        __half hi = __float2half_rn(v);
        __half lo = __float2half_rn(v - __half2float(hi));
        size_t o = ((size_t)b * HW + h * Ww + w) * C1 + c;
        g_xTh[o] = hi;
        g_xTl[o] = lo;
    }
}

// ============================================================================
// Kernel 0b: deform weights -> m16n8k16 B frags, fp16 single-term
// ============================================================================
__global__ __launch_bounds__(256) void prep_wfrag_kernel(const float* __restrict__ wgt)
{
    int i = blockIdx.x * 256 + threadIdx.x;
    if (i >= 9 * 8 * 16 * 32) return;
    int lane = i & 31;
    int nf   = (i >> 5) & 15;
    int kc   = (i >> 9) & 7;
    int tap  = i >> 12;
    int n  = nf * 8 + (lane >> 2);
    int kb = kc * 16 + (lane & 3) * 2;

    __half h00 = __float2half_rn(wgt[(n * 128 + kb + 0) * 9 + tap]);
    __half h01 = __float2half_rn(wgt[(n * 128 + kb + 1) * 9 + tap]);
    __half h10 = __float2half_rn(wgt[(n * 128 + kb + 8) * 9 + tap]);
    __half h11 = __float2half_rn(wgt[(n * 128 + kb + 9) * 9 + tap]);

    uint2 v;
    v.x = ((uint32_t)__half_as_ushort(h01) << 16) | (uint32_t)__half_as_ushort(h00);
    v.y = ((uint32_t)__half_as_ushort(h11) << 16) | (uint32_t)__half_as_ushort(h10);
    g_wF[i] = v;
}

// ============================================================================
// Kernel 0c: offset weights -> B frags, fp16 hi/lo, N pad 18->32
// ============================================================================
__global__ __launch_bounds__(256) void prep_ofrag_kernel(const float* __restrict__ ow)
{
    int i = blockIdx.x * 256 + threadIdx.x;
    if (i >= 9 * 8 * 4 * 32) return;
    int lane = i & 31;
    int nf   = (i >> 5) & 3;
    int kc   = (i >> 7) & 7;
    int tap  = i >> 10;
    int n  = nf * 8 + (lane >> 2);
    int kb = kc * 16 + (lane & 3) * 2;

    float w00 = 0.f, w01 = 0.f, w10 = 0.f, w11 = 0.f;
    if (n < OFFC) {
        w00 = ow[(n * 128 + kb + 0) * 9 + tap];
        w01 = ow[(n * 128 + kb + 1) * 9 + tap];
        w10 = ow[(n * 128 + kb + 8) * 9 + tap];
        w11 = ow[(n * 128 + kb + 9) * 9 + tap];
    }
    uint4 v;
    uint32_t l01, l89;
    v.x = hsplit2(w00, w01, l01);
    v.y = hsplit2(w10, w11, l89);
    v.z = l01;
    v.w = l89;
    g_oF[i] = v;
}

// ============================================================================
// FUSED kernel: 64 px x 128 oc per block, 256 threads, 4 CTAs/SM.
// Phase 1: offset conv (fixed-window A hi/lo -> 3-term MMA, N=32 pad) ->
//          offsets (+bias) into s_off[64][20].
// Phase 2: deform conv (bilinear fp16 gather, single-term MMA), meta from
//          s_off, double-buffered A, 1 sync/tap, direct-fragment epilogue.
// ============================================================================
#define MPX 64
#define LDA 136
#define ABYTES (MPX * LDA * 2)            // 17408

#define SM_BIAS 0
#define SM_OB   512
#define SM_OFF  640                        // 64 x 20 floats = 5120
#define SM_BUF0 5888
#define SM_BUF1 (SM_BUF0 + ABYTES)         // 23296
#define SMEM_TOTAL_F (SM_BUF1 + ABYTES)    // 40704

__global__ __launch_bounds__(256, 4)
void fused_dsconv_kernel(const float* __restrict__ ob,
                         const float* __restrict__ bias,
                         float* __restrict__ out)
{
    extern __shared__ char smem[];
    const uint32_t sb = smem_u32(smem);
    float* s_bias = reinterpret_cast<float*>(smem + SM_BIAS);
    float* s_ob   = reinterpret_cast<float*>(smem + SM_OB);
    float* s_off  = reinterpret_cast<float*>(smem + SM_OFF);

    const int t    = threadIdx.x;
    const int wid  = t >> 5;
    const int lane = t & 31;
    const int b    = blockIdx.y;
    const int pix0 = blockIdx.x * MPX;

    const __half* xh = g_xTh + (size_t)b * HW * C1;
    const __half* xl = g_xTl + (size_t)b * HW * C1;

    if (t < 128) s_bias[t] = bias[t];
    if (t < OFFC) s_ob[t] = ob[t];

    // ldmatrix lane addressing (shared by both phases)
    const int tile = lane >> 3;
    const int rr   = ((tile & 1) << 3) + (lane & 7);
    const int cbm  = (tile >> 1) << 3;

    // =========================== PHASE 1: offsets ===========================
    {
        const int wm = wid & 3;    // 4 m-frags of 16 px
        const int wn = wid >> 2;   // 2 n-groups (2 nfrags = 16 oc each)
        const int m0 = wm * 16;

        float oacc[2][4];
#pragma unroll
        for (int j = 0; j < 2; j++)
#pragma unroll
            for (int r = 0; r < 4; r++) oacc[j][r] = 0.f;

#pragma unroll 1
        for (int tap = 0; tap < 9; tap++) {
            // ---- A: fixed-window hi/lo rows into buf0/buf1 ----
            {
                __half* Ah = reinterpret_cast<__half*>(smem + SM_BUF0);
                __half* Al = reinterpret_cast<__half*>(smem + SM_BUF1);
                const int ki = tap / 3;
                const int kj = tap % 3;
                const int pxbase = wid * 8;
#pragma unroll 2
                for (int i = 0; i < 8; i++) {
                    const int px  = pxbase + i;
                    const int pix = pix0 + px;
                    const int ho  = pix / Ww;
                    const int wo  = pix - ho * Ww;
                    const int sy  = ho - 1 + ki;
                    const int sx  = wo - 1 + kj;
                    uint2 vh = make_uint2(0u, 0u), vl = make_uint2(0u, 0u);
                    if (sy >= 0 && sy < Hh && sx >= 0 && sx < Ww) {
                        const size_t ro = (size_t)(sy * Ww + sx) * C1;
                        vh = *(reinterpret_cast<const uint2*>(xh + ro) + lane);
                        vl = *(reinterpret_cast<const uint2*>(xl + ro) + lane);
                    }
                    *reinterpret_cast<uint2*>(Ah + px * LDA + lane * 4) = vh;
                    *reinterpret_cast<uint2*>(Al + px * LDA + lane * 4) = vl;
                }
            }
            __syncthreads();

            // ---- MMA: 8 kc x 2 nfrags x 3 terms ----
#pragma unroll 1
            for (int kc = 0; kc < 8; kc++) {
                uint32_t bh[2][2], bl[2][2];
                const uint4* wf = g_oF + (((size_t)tap * 8 + kc) * 4 + wn * 2) * 32 + lane;
#pragma unroll
                for (int j = 0; j < 2; j++) {
                    uint4 bv = wf[j * 32];
                    bh[j][0] = bv.x; bh[j][1] = bv.y;
                    bl[j][0] = bv.z; bl[j][1] = bv.w;
                }
                uint32_t ah[4], al[4];
                uint32_t off = ((m0 + rr) * LDA + kc * 16 + cbm) * 2;
                ldsm_x4(ah, sb + SM_BUF0 + off);
                ldsm_x4(al, sb + SM_BUF1 + off);
#pragma unroll
                for (int j = 0; j < 2; j++) {
                    mma16816h(oacc[j], ah, bh[j]);
                    mma16816h(oacc[j], ah, bl[j]);
                    mma16816h(oacc[j], al, bh[j]);
                }
            }
            __syncthreads();
        }

        // ---- offsets (+bias) -> s_off[px][20] ----
        {
            const int r0 = lane >> 2;
            const int c0 = (lane & 3) * 2;
#pragma unroll
            for (int j = 0; j < 2; j++) {
                const int col = wn * 16 + j * 8 + c0;
                if (col < OFFC) {
                    s_off[(m0 + r0) * 20 + col]     = oacc[j][0] + s_ob[col];
                    s_off[(m0 + r0 + 8) * 20 + col] = oacc[j][2] + s_ob[col];
                }
                if (col + 1 < OFFC) {
                    s_off[(m0 + r0) * 20 + col + 1]     = oacc[j][1] + s_ob[col + 1];
                    s_off[(m0 + r0 + 8) * 20 + col + 1] = oacc[j][3] + s_ob[col + 1];
                }
            }
        }
        __syncthreads();
    }

    // =========================== PHASE 2: deform ============================
    const int wm = wid & 1;    // 2 m-groups of 32 px
    const int wn = wid >> 1;   // 4 n-groups of 32 oc

    float acc[2][4][4];
#pragma unroll
    for (int mt = 0; mt < 2; mt++)
#pragma unroll
        for (int j = 0; j < 4; j++)
#pragma unroll
            for (int r = 0; r < 4; r++) acc[mt][j][r] = 0.f;

    // per-warp register meta: lane l8 handles local px = wid*8 + l8
    const int l8  = lane & 7;
    const int pxl = wid * 8 + l8;
    const int pxm = pix0 + pxl;
    const int hom = pxm / Ww;
    const int wom = pxm - hom * Ww;
    float m_w0, m_w1, m_w2, m_w3;
    int   m_o0, m_o1, m_o2, m_o3;

    auto compute_meta = [&](int tap) {
        const int ki = tap / 3;
        const int kj = tap % 3;
        float dy = s_off[pxl * 20 + 2 * tap];
        float dx = s_off[pxl * 20 + 2 * tap + 1];
        float py  = (float)(hom - 1 + ki) + dy;
        float pxx = (float)(wom - 1 + kj) + dx;
        float y0 = floorf(py);
        float x0 = floorf(pxx);
        float wy1 = py - y0, wy0 = 1.f - wy1;
        float wx1 = pxx - x0, wx0 = 1.f - wx1;

        float yc0 = y0, yc1 = y0 + 1.f, xc0 = x0, xc1 = x0 + 1.f;
        bool vy0 = (yc0 >= 0.f) && (yc0 < (float)Hh);
        bool vy1 = (yc1 >= 0.f) && (yc1 < (float)Hh);
        bool vx0 = (xc0 >= 0.f) && (xc0 < (float)Ww);
        bool vx1 = (xc1 >= 0.f) && (xc1 < (float)Ww);
        int iy0 = (int)fminf(fmaxf(yc0, 0.f), (float)(Hh - 1));
        int iy1 = (int)fminf(fmaxf(yc1, 0.f), (float)(Hh - 1));
        int ix0 = (int)fminf(fmaxf(xc0, 0.f), (float)(Ww - 1));
        int ix1 = (int)fminf(fmaxf(xc1, 0.f), (float)(Ww - 1));
        m_w0 = (vy0 && vx0) ? wy0 * wx0 : 0.f;  m_o0 = iy0 * Ww + ix0;
        m_w1 = (vy0 && vx1) ? wy0 * wx1 : 0.f;  m_o1 = iy0 * Ww + ix1;
        m_w2 = (vy1 && vx0) ? wy1 * wx0 : 0.f;  m_o2 = iy1 * Ww + ix0;
        m_w3 = (vy1 && vx1) ? wy1 * wx1 : 0.f;  m_o3 = iy1 * Ww + ix1;
    };

    auto gather_into = [&](int bufsel) {
        __half* Ah = reinterpret_cast<__half*>(
            smem + (bufsel ? SM_BUF1 : SM_BUF0));
        const int pxbase = wid * 8;
#pragma unroll 2
        for (int i = 0; i < 8; i++) {
            const int px = pxbase + i;
            const float w0 = __shfl_sync(0xffffffffu, m_w0, i);
            const float w1 = __shfl_sync(0xffffffffu, m_w1, i);
            const float w2 = __shfl_sync(0xffffffffu, m_w2, i);
            const float w3 = __shfl_sync(0xffffffffu, m_w3, i);
            const int o0 = __shfl_sync(0xffffffffu, m_o0, i);
            const int o1 = __shfl_sync(0xffffffffu, m_o1, i);
            const int o2 = __shfl_sync(0xffffffffu, m_o2, i);
            const int o3 = __shfl_sync(0xffffffffu, m_o3, i);
            uint2 r0 = *(reinterpret_cast<const uint2*>(xh + (size_t)o0 * C1) + lane);
            uint2 r1 = *(reinterpret_cast<const uint2*>(xh + (size_t)o1 * C1) + lane);
            uint2 r2 = *(reinterpret_cast<const uint2*>(xh + (size_t)o2 * C1) + lane);
            uint2 r3 = *(reinterpret_cast<const uint2*>(xh + (size_t)o3 * C1) + lane);
            float2 v0a = __half22float2(*reinterpret_cast<__half2*>(&r0.x));
            float2 v0b = __half22float2(*reinterpret_cast<__half2*>(&r0.y));
            float2 v1a = __half22float2(*reinterpret_cast<__half2*>(&r1.x));
            float2 v1b = __half22float2(*reinterpret_cast<__half2*>(&r1.y));
            float2 v2a = __half22float2(*reinterpret_cast<__half2*>(&r2.x));
            float2 v2b = __half22float2(*reinterpret_cast<__half2*>(&r2.y));
            float2 v3a = __half22float2(*reinterpret_cast<__half2*>(&r3.x));
            float2 v3b = __half22float2(*reinterpret_cast<__half2*>(&r3.y));
            float a0 = w0 * v0a.x; a0 = fmaf(w1, v1a.x, a0);
            a0 = fmaf(w2, v2a.x, a0); a0 = fmaf(w3, v3a.x, a0);
            float a1 = w0 * v0a.y; a1 = fmaf(w1, v1a.y, a1);
            a1 = fmaf(w2, v2a.y, a1); a1 = fmaf(w3, v3a.y, a1);
            float a2 = w0 * v0b.x; a2 = fmaf(w1, v1b.x, a2);
            a2 = fmaf(w2, v2b.x, a2); a2 = fmaf(w3, v3b.x, a2);
            float a3 = w0 * v0b.y; a3 = fmaf(w1, v1b.y, a3);
            a3 = fmaf(w2, v2b.y, a3); a3 = fmaf(w3, v3b.y, a3);
            __half2 h01 = __floats2half2_rn(a0, a1);
            __half2 h23 = __floats2half2_rn(a2, a3);
            uint2 pk;
            pk.x = *reinterpret_cast<uint32_t*>(&h01);
            pk.y = *reinterpret_cast<uint32_t*>(&h23);
            *reinterpret_cast<uint2*>(Ah + px * LDA + lane * 4) = pk;
        }
    };

    // prologue
    compute_meta(0);
    gather_into(0);
    __syncthreads();

    // pipelined main loop: 1 sync per tap
#pragma unroll 1
    for (int tap = 0; tap < 9; tap++) {
        const int cur = tap & 1;
        if (tap < 8) {
            compute_meta(tap + 1);
            gather_into(1 - cur);
        }

        const uint32_t abase = sb + (cur ? SM_BUF1 : SM_BUF0);
        const int m0 = wm * 32;
#pragma unroll 1
        for (int kc = 0; kc < 8; kc++) {
            uint32_t bf[4][2];
            const uint2* wf = g_wF + (((size_t)tap * 8 + kc) * 16 + wn * 4) * 32 + lane;
#pragma unroll
            for (int j = 0; j < 4; j++) {
                uint2 bv = wf[j * 32];
                bf[j][0] = bv.x; bf[j][1] = bv.y;
            }
            uint32_t af[2][4];
#pragma unroll
            for (int mt = 0; mt < 2; mt++) {
                uint32_t off = ((m0 + mt * 16 + rr) * LDA + kc * 16 + cbm) * 2;
                ldsm_x4(af[mt], abase + off);
            }
#pragma unroll
            for (int mt = 0; mt < 2; mt++) {
#pragma unroll
                for (int j = 0; j < 4; j++) {
                    mma16816h(acc[mt][j], af[mt], bf[j]);
                }
            }
        }
        __syncthreads();
    }

    // ---- epilogue: direct fragment -> gmem stores (+bias), no smem ----
    {
        const int r0 = lane >> 2;
        const int c0 = (lane & 3) * 2;
#pragma unroll
        for (int mt = 0; mt < 2; mt++) {
            const int row = wm * 32 + mt * 16 + r0;
#pragma unroll
            for (int j = 0; j < 4; j++) {
                const int col = wn * 32 + j * 8 + c0;
                const float b0 = s_bias[col];
                const float b1 = s_bias[col + 1];
                float* o0 = out + (size_t)(b * C2 + col) * HW + pix0 + row;
                float* o1 = out + (size_t)(b * C2 + col + 1) * HW + pix0 + row;
                o0[0] = acc[mt][j][0] + b0;
                o1[0] = acc[mt][j][1] + b1;
                o0[8] = acc[mt][j][2] + b0;
                o1[8] = acc[mt][j][3] + b1;
            }
        }
    }
}

// ============================================================================
// Launch: prep kernels then single fused kernel. No streams, no events.
// ============================================================================
extern "C" void kernel_launch(void* const* d_in, const int* in_sizes, int n_in,
                              void* d_out, int out_size) {
    const float* x    = (const float*)d_in[0];
    const float* ow   = (const float*)d_in[1];
    const float* ob   = (const float*)d_in[2];
    const float* wgt  = (const float*)d_in[3];
    const float* bias = (const float*)d_in[4];
    float* out = (float*)d_out;

    dim3 gn(Hh, BATCH);
    nhwc_kernel<<<gn, 256>>>(x);
    prep_wfrag_kernel<<<(9 * 8 * 16 * 32 + 255) / 256, 256>>>(wgt);
    prep_ofrag_kernel<<<(9 * 8 * 4 * 32 + 255) / 256, 256>>>(ow);

    cudaFuncSetAttribute(fused_dsconv_kernel,
                         cudaFuncAttributeMaxDynamicSharedMemorySize,
                         SMEM_TOTAL_F);
    dim3 gf(HW / MPX, BATCH);
    fused_dsconv_kernel<<<gf, 256, SMEM_TOTAL_F>>>(ob, bias, out);
}

// round 17
// speedup vs baseline: 1.1019x; 1.0209x over previous
#include <cuda_runtime.h>
#include <cuda_fp16.h>
#include <cstdint>

// ---------------------------------------------------------------------------
// DSConv2d: offset conv (3x3, 128->18) + deformable conv (3x3, 128->128)
// B=16, C1=C2=128, H=W=80, fp32.
// Round 17: r16 fused kernel + cp.async 16B zfill for phase-1 A builds and
// hoisted per-px address math (alu/L1 instruction-stream reduction).
// ---------------------------------------------------------------------------

#define Hh 80
#define Ww 80
#define HW 6400
#define C1 128
#define C2 128
#define BATCH 16
#define OFFC 18

static __device__ __half g_xTh[BATCH * HW * C1];        // 26.2 MB NHWC fp16 hi
static __device__ __half g_xTl[BATCH * HW * C1];        // 26.2 MB NHWC fp16 lo
static __device__ uint2  g_wF[9 * 8 * 16 * 32];         // deform B frags (fp16)
static __device__ uint4  g_oF[9 * 8 * 4 * 32];          // offset B frags (hi/lo), N=32

// ============================================================================
// common helpers
// ============================================================================
__device__ __forceinline__ uint32_t smem_u32(const void* p) {
    uint32_t a;
    asm("{ .reg .u64 t; cvta.to.shared.u64 t, %1; cvt.u32.u64 %0, t; }"
        : "=r"(a) : "l"(p));
    return a;
}

__device__ __forceinline__ void ldsm_x4(uint32_t* r, uint32_t saddr) {
    asm volatile("ldmatrix.sync.aligned.m8n8.x4.shared.b16 {%0,%1,%2,%3}, [%4];"
                 : "=r"(r[0]), "=r"(r[1]), "=r"(r[2]), "=r"(r[3])
                 : "r"(saddr));
}

__device__ __forceinline__ void mma16816h(float* d, const uint32_t* a,
                                          const uint32_t* b) {
    asm volatile(
        "mma.sync.aligned.m16n8k16.row.col.f32.f16.f16.f32 "
        "{%0,%1,%2,%3}, {%4,%5,%6,%7}, {%8,%9}, {%0,%1,%2,%3};"
        : "+f"(d[0]), "+f"(d[1]), "+f"(d[2]), "+f"(d[3])
        : "r"(a[0]), "r"(a[1]), "r"(a[2]), "r"(a[3]),
          "r"(b[0]), "r"(b[1]));
}

// cp.async 16B with zfill: src_bytes=16 copies, src_bytes=0 zero-fills.
__device__ __forceinline__ void cp16(uint32_t dst, const void* src, int src_bytes) {
    asm volatile("cp.async.ca.shared.global [%0], [%1], 16, %2;"
                 :: "r"(dst), "l"(src), "r"(src_bytes));
}
#define CP_COMMIT() asm volatile("cp.async.commit_group;" ::: "memory")
#define CP_WAIT0()  asm volatile("cp.async.wait_group 0;" ::: "memory")

__device__ __forceinline__ uint32_t hsplit2(float va, float vb, uint32_t& lo) {
    __half ha = __float2half_rn(va);
    __half hb = __float2half_rn(vb);
    __half la = __float2half_rn(va - __half2float(ha));
    __half lb = __float2half_rn(vb - __half2float(hb));
    lo = ((uint32_t)__half_as_ushort(lb) << 16) | (uint32_t)__half_as_ushort(la);
    return ((uint32_t)__half_as_ushort(hb) << 16) | (uint32_t)__half_as_ushort(ha);
}

// ============================================================================
// Kernel 0a: NCHW -> NHWC fp16 hi/lo planes
// ============================================================================
__global__ __launch_bounds__(256) void nhwc_kernel(const float* __restrict__ x)
{
    __shared__ float tile[128][81];
    const int h = blockIdx.x;
    const int b = blockIdx.y;
    const int t = threadIdx.x;

    for (int idx = t; idx < 128 * 80; idx += 256) {
        int c = idx / 80;
        int w = idx - c * 80;
        tile[c][w] = x[((size_t)(b * C1 + c) * Hh + h) * Ww + w];
    }
    __syncthreads();
    for (int idx = t; idx < 80 * 128; idx += 256) {
        int w = idx >> 7;
        int c = idx & 127;
        float v = tile[c][w];
        __half hi = __float2half_rn(v);
        __half lo = __float2half_rn(v - __half2float(hi));
        size_t o = ((size_t)b * HW + h * Ww + w) * C1 + c;
        g_xTh[o] = hi;
        g_xTl[o] = lo;
    }
}

// ============================================================================
// Kernel 0b: deform weights -> m16n8k16 B frags, fp16 single-term
// ============================================================================
__global__ __launch_bounds__(256) void prep_wfrag_kernel(const float* __restrict__ wgt)
{
    int i = blockIdx.x * 256 + threadIdx.x;
    if (i >= 9 * 8 * 16 * 32) return;
    int lane = i & 31;
    int nf   = (i >> 5) & 15;
    int kc   = (i >> 9) & 7;
    int tap  = i >> 12;
    int n  = nf * 8 + (lane >> 2);
    int kb = kc * 16 + (lane & 3) * 2;

    __half h00 = __float2half_rn(wgt[(n * 128 + kb + 0) * 9 + tap]);
    __half h01 = __float2half_rn(wgt[(n * 128 + kb + 1) * 9 + tap]);
    __half h10 = __float2half_rn(wgt[(n * 128 + kb + 8) * 9 + tap]);
    __half h11 = __float2half_rn(wgt[(n * 128 + kb + 9) * 9 + tap]);

    uint2 v;
    v.x = ((uint32_t)__half_as_ushort(h01) << 16) | (uint32_t)__half_as_ushort(h00);
    v.y = ((uint32_t)__half_as_ushort(h11) << 16) | (uint32_t)__half_as_ushort(h10);
    g_wF[i] = v;
}

// ============================================================================
// Kernel 0c: offset weights -> B frags, fp16 hi/lo, N pad 18->32
// ============================================================================
__global__ __launch_bounds__(256) void prep_ofrag_kernel(const float* __restrict__ ow)
{
    int i = blockIdx.x * 256 + threadIdx.x;
    if (i >= 9 * 8 * 4 * 32) return;
    int lane = i & 31;
    int nf   = (i >> 5) & 3;
    int kc   = (i >> 7) & 7;
    int tap  = i >> 10;
    int n  = nf * 8 + (lane >> 2);
    int kb = kc * 16 + (lane & 3) * 2;

    float w00 = 0.f, w01 = 0.f, w10 = 0.f, w11 = 0.f;
    if (n < OFFC) {
        w00 = ow[(n * 128 + kb + 0) * 9 + tap];
        w01 = ow[(n * 128 + kb + 1) * 9 + tap];
        w10 = ow[(n * 128 + kb + 8) * 9 + tap];
        w11 = ow[(n * 128 + kb + 9) * 9 + tap];
    }
    uint4 v;
    uint32_t l01, l89;
    v.x = hsplit2(w00, w01, l01);
    v.y = hsplit2(w10, w11, l89);
    v.z = l01;
    v.w = l89;
    g_oF[i] = v;
}

// ============================================================================
// FUSED kernel: 64 px x 128 oc per block, 256 threads, 4 CTAs/SM.
// Phase 1: offset conv; A built via cp.async 16B zfill (pure row copies).
// Phase 2: deform conv (bilinear fp16 gather, single-term MMA), meta from
//          s_off, double-buffered A, 1 sync/tap, direct-fragment epilogue.
// ============================================================================
#define MPX 64
#define LDA 136
#define ABYTES (MPX * LDA * 2)            // 17408

#define SM_BIAS 0
#define SM_OB   512
#define SM_OFF  640                        // 64 x 20 floats = 5120
#define SM_BUF0 5888
#define SM_BUF1 (SM_BUF0 + ABYTES)         // 23296
#define SMEM_TOTAL_F (SM_BUF1 + ABYTES)    // 40704

__global__ __launch_bounds__(256, 4)
void fused_dsconv_kernel(const float* __restrict__ ob,
                         const float* __restrict__ bias,
                         float* __restrict__ out)
{
    extern __shared__ char smem[];
    const uint32_t sb = smem_u32(smem);
    float* s_bias = reinterpret_cast<float*>(smem + SM_BIAS);
    float* s_ob   = reinterpret_cast<float*>(smem + SM_OB);
    float* s_off  = reinterpret_cast<float*>(smem + SM_OFF);

    const int t    = threadIdx.x;
    const int wid  = t >> 5;
    const int lane = t & 31;
    const int b    = blockIdx.y;
    const int pix0 = blockIdx.x * MPX;

    const __half* xh = g_xTh + (size_t)b * HW * C1;
    const __half* xl = g_xTl + (size_t)b * HW * C1;

    if (t < 128) s_bias[t] = bias[t];
    if (t < OFFC) s_ob[t] = ob[t];

    // ldmatrix lane addressing (shared by both phases)
    const int tile = lane >> 3;
    const int rr   = ((tile & 1) << 3) + (lane & 7);
    const int cbm  = (tile >> 1) << 3;

    // =========================== PHASE 1: offsets ===========================
    {
        const int wm = wid & 3;    // 4 m-frags of 16 px
        const int wn = wid >> 2;   // 2 n-groups (2 nfrags = 16 oc each)
        const int m0 = wm * 16;

        float oacc[2][4];
#pragma unroll
        for (int j = 0; j < 2; j++)
#pragma unroll
            for (int r = 0; r < 4; r++) oacc[j][r] = 0.f;

        // ---- hoisted per-lane copy addressing: warp owns 8 px; 16 lanes
        //      per row; this lane serves px cp_px[it] = wid*8 + it*2 + (lane>>4)
        int cp_hom1[4], cp_wom1[4];
        uint32_t cp_dst[4];
        {
            const int sub = lane >> 4;       // 0 or 1
            const int col16 = (lane & 15) * 16;  // byte offset within 256B row
#pragma unroll
            for (int it = 0; it < 4; it++) {
                const int px  = wid * 8 + it * 2 + sub;
                const int pix = pix0 + px;
                const int ho  = pix / Ww;
                cp_hom1[it] = ho - 1;
                cp_wom1[it] = (pix - ho * Ww) - 1;
                cp_dst[it]  = sb + SM_BUF0 + (uint32_t)(px * LDA * 2) + col16;
            }
        }
        const int col16 = (lane & 15) * 16;

#pragma unroll 1
        for (int tap = 0; tap < 9; tap++) {
            const int ki = tap / 3;
            const int kj = tap % 3;
            // ---- A build: cp.async 16B per lane, hi+lo planes ----
#pragma unroll
            for (int it = 0; it < 4; it++) {
                const int sy = cp_hom1[it] + ki;
                const int sx = cp_wom1[it] + kj;
                const bool valid = (sy >= 0) && (sy < Hh) && (sx >= 0) && (sx < Ww);
                const int n = valid ? 16 : 0;
                const int syc = min(max(sy, 0), Hh - 1);
                const int sxc = min(max(sx, 0), Ww - 1);
                const size_t ro = (size_t)(syc * Ww + sxc) * C1;
                cp16(cp_dst[it],
                     reinterpret_cast<const char*>(xh + ro) + col16, n);
                cp16(cp_dst[it] + ABYTES,
                     reinterpret_cast<const char*>(xl + ro) + col16, n);
            }
            CP_COMMIT();
            CP_WAIT0();
            __syncthreads();

            // ---- MMA: 8 kc x 2 nfrags x 3 terms ----
#pragma unroll 1
            for (int kc = 0; kc < 8; kc++) {
                uint32_t bh[2][2], bl[2][2];
                const uint4* wf = g_oF + (((size_t)tap * 8 + kc) * 4 + wn * 2) * 32 + lane;
#pragma unroll
                for (int j = 0; j < 2; j++) {
                    uint4 bv = wf[j * 32];
                    bh[j][0] = bv.x; bh[j][1] = bv.y;
                    bl[j][0] = bv.z; bl[j][1] = bv.w;
                }
                uint32_t ah[4], al[4];
                uint32_t off = ((m0 + rr) * LDA + kc * 16 + cbm) * 2;
                ldsm_x4(ah, sb + SM_BUF0 + off);
                ldsm_x4(al, sb + SM_BUF1 + off);
#pragma unroll
                for (int j = 0; j < 2; j++) {
                    mma16816h(oacc[j], ah, bh[j]);
                    mma16816h(oacc[j], ah, bl[j]);
                    mma16816h(oacc[j], al, bh[j]);
                }
            }
            __syncthreads();
        }

        // ---- offsets (+bias) -> s_off[px][20] ----
        {
            const int r0 = lane >> 2;
            const int c0 = (lane & 3) * 2;
#pragma unroll
            for (int j = 0; j < 2; j++) {
                const int col = wn * 16 + j * 8 + c0;
                if (col < OFFC) {
                    s_off[(m0 + r0) * 20 + col]     = oacc[j][0] + s_ob[col];
                    s_off[(m0 + r0 + 8) * 20 + col] = oacc[j][2] + s_ob[col];
                }
                if (col + 1 < OFFC) {
                    s_off[(m0 + r0) * 20 + col + 1]     = oacc[j][1] + s_ob[col + 1];
                    s_off[(m0 + r0 + 8) * 20 + col + 1] = oacc[j][3] + s_ob[col + 1];
                }
            }
        }
        __syncthreads();
    }

    // =========================== PHASE 2: deform ============================
    const int wm = wid & 1;    // 2 m-groups of 32 px
    const int wn = wid >> 1;   // 4 n-groups of 32 oc

    float acc[2][4][4];
#pragma unroll
    for (int mt = 0; mt < 2; mt++)
#pragma unroll
        for (int j = 0; j < 4; j++)
#pragma unroll
            for (int r = 0; r < 4; r++) acc[mt][j][r] = 0.f;

    // per-warp register meta: lane l8 handles local px = wid*8 + l8
    const int l8  = lane & 7;
    const int pxl = wid * 8 + l8;
    const int pxm = pix0 + pxl;
    const int hom = pxm / Ww;
    const int wom = pxm - hom * Ww;
    float m_w0, m_w1, m_w2, m_w3;
    int   m_o0, m_o1, m_o2, m_o3;

    auto compute_meta = [&](int tap) {
        const int ki = tap / 3;
        const int kj = tap % 3;
        float dy = s_off[pxl * 20 + 2 * tap];
        float dx = s_off[pxl * 20 + 2 * tap + 1];
        float py  = (float)(hom - 1 + ki) + dy;
        float pxx = (float)(wom - 1 + kj) + dx;
        float y0 = floorf(py);
        float x0 = floorf(pxx);
        float wy1 = py - y0, wy0 = 1.f - wy1;
        float wx1 = pxx - x0, wx0 = 1.f - wx1;

        float yc0 = y0, yc1 = y0 + 1.f, xc0 = x0, xc1 = x0 + 1.f;
        bool vy0 = (yc0 >= 0.f) && (yc0 < (float)Hh);
        bool vy1 = (yc1 >= 0.f) && (yc1 < (float)Hh);
        bool vx0 = (xc0 >= 0.f) && (xc0 < (float)Ww);
        bool vx1 = (xc1 >= 0.f) && (xc1 < (float)Ww);
        int iy0 = (int)fminf(fmaxf(yc0, 0.f), (float)(Hh - 1));
        int iy1 = (int)fminf(fmaxf(yc1, 0.f), (float)(Hh - 1));
        int ix0 = (int)fminf(fmaxf(xc0, 0.f), (float)(Ww - 1));
        int ix1 = (int)fminf(fmaxf(xc1, 0.f), (float)(Ww - 1));
        m_w0 = (vy0 && vx0) ? wy0 * wx0 : 0.f;  m_o0 = iy0 * Ww + ix0;
        m_w1 = (vy0 && vx1) ? wy0 * wx1 : 0.f;  m_o1 = iy0 * Ww + ix1;
        m_w2 = (vy1 && vx0) ? wy1 * wx0 : 0.f;  m_o2 = iy1 * Ww + ix0;
        m_w3 = (vy1 && vx1) ? wy1 * wx1 : 0.f;  m_o3 = iy1 * Ww + ix1;
    };

    auto gather_into = [&](int bufsel) {
        __half* Ah = reinterpret_cast<__half*>(
            smem + (bufsel ? SM_BUF1 : SM_BUF0));
        const int pxbase = wid * 8;
#pragma unroll 2
        for (int i = 0; i < 8; i++) {
            const int px = pxbase + i;
            const float w0 = __shfl_sync(0xffffffffu, m_w0, i);
            const float w1 = __shfl_sync(0xffffffffu, m_w1, i);
            const float w2 = __shfl_sync(0xffffffffu, m_w2, i);
            const float w3 = __shfl_sync(0xffffffffu, m_w3, i);
            const int o0 = __shfl_sync(0xffffffffu, m_o0, i);
            const int o1 = __shfl_sync(0xffffffffu, m_o1, i);
            const int o2 = __shfl_sync(0xffffffffu, m_o2, i);
            const int o3 = __shfl_sync(0xffffffffu, m_o3, i);
            uint2 r0 = *(reinterpret_cast<const uint2*>(xh + (size_t)o0 * C1) + lane);
            uint2 r1 = *(reinterpret_cast<const uint2*>(xh + (size_t)o1 * C1) + lane);
            uint2 r2 = *(reinterpret_cast<const uint2*>(xh + (size_t)o2 * C1) + lane);
            uint2 r3 = *(reinterpret_cast<const uint2*>(xh + (size_t)o3 * C1) + lane);
            float2 v0a = __half22float2(*reinterpret_cast<__half2*>(&r0.x));
            float2 v0b = __half22float2(*reinterpret_cast<__half2*>(&r0.y));
            float2 v1a = __half22float2(*reinterpret_cast<__half2*>(&r1.x));
            float2 v1b = __half22float2(*reinterpret_cast<__half2*>(&r1.y));
            float2 v2a = __half22float2(*reinterpret_cast<__half2*>(&r2.x));
            float2 v2b = __half22float2(*reinterpret_cast<__half2*>(&r2.y));
            float2 v3a = __half22float2(*reinterpret_cast<__half2*>(&r3.x));
            float2 v3b = __half22float2(*reinterpret_cast<__half2*>(&r3.y));
            float a0 = w0 * v0a.x; a0 = fmaf(w1, v1a.x, a0);
            a0 = fmaf(w2, v2a.x, a0); a0 = fmaf(w3, v3a.x, a0);
            float a1 = w0 * v0a.y; a1 = fmaf(w1, v1a.y, a1);
            a1 = fmaf(w2, v2a.y, a1); a1 = fmaf(w3, v3a.y, a1);
            float a2 = w0 * v0b.x; a2 = fmaf(w1, v1b.x, a2);
            a2 = fmaf(w2, v2b.x, a2); a2 = fmaf(w3, v3b.x, a2);
            float a3 = w0 * v0b.y; a3 = fmaf(w1, v1b.y, a3);
            a3 = fmaf(w2, v2b.y, a3); a3 = fmaf(w3, v3b.y, a3);
            __half2 h01 = __floats2half2_rn(a0, a1);
            __half2 h23 = __floats2half2_rn(a2, a3);
            uint2 pk;
            pk.x = *reinterpret_cast<uint32_t*>(&h01);
            pk.y = *reinterpret_cast<uint32_t*>(&h23);
            *reinterpret_cast<uint2*>(Ah + px * LDA + lane * 4) = pk;
        }
    };

    // prologue
    compute_meta(0);
    gather_into(0);
    __syncthreads();

    // pipelined main loop: 1 sync per tap
#pragma unroll 1
    for (int tap = 0; tap < 9; tap++) {
        const int cur = tap & 1;
        if (tap < 8) {
            compute_meta(tap + 1);
            gather_into(1 - cur);
        }

        const uint32_t abase = sb + (cur ? SM_BUF1 : SM_BUF0);
        const int m0 = wm * 32;
#pragma unroll 1
        for (int kc = 0; kc < 8; kc++) {
            uint32_t bf[4][2];
            const uint2* wf = g_wF + (((size_t)tap * 8 + kc) * 16 + wn * 4) * 32 + lane;
#pragma unroll
            for (int j = 0; j < 4; j++) {
                uint2 bv = wf[j * 32];
                bf[j][0] = bv.x; bf[j][1] = bv.y;
            }
            uint32_t af[2][4];
#pragma unroll
            for (int mt = 0; mt < 2; mt++) {
                uint32_t off = ((m0 + mt * 16 + rr) * LDA + kc * 16 + cbm) * 2;
                ldsm_x4(af[mt], abase + off);
            }
#pragma unroll
            for (int mt = 0; mt < 2; mt++) {
#pragma unroll
                for (int j = 0; j < 4; j++) {
                    mma16816h(acc[mt][j], af[mt], bf[j]);
                }
            }
        }
        __syncthreads();
    }

    // ---- epilogue: direct fragment -> gmem stores (+bias), no smem ----
    {
        const int r0 = lane >> 2;
        const int c0 = (lane & 3) * 2;
#pragma unroll
        for (int mt = 0; mt < 2; mt++) {
            const int row = wm * 32 + mt * 16 + r0;
#pragma unroll
            for (int j = 0; j < 4; j++) {
                const int col = wn * 32 + j * 8 + c0;
                const float b0 = s_bias[col];
                const float b1 = s_bias[col + 1];
                float* o0 = out + (size_t)(b * C2 + col) * HW + pix0 + row;
                float* o1 = out + (size_t)(b * C2 + col + 1) * HW + pix0 + row;
                o0[0] = acc[mt][j][0] + b0;
                o1[0] = acc[mt][j][1] + b1;
                o0[8] = acc[mt][j][2] + b0;
                o1[8] = acc[mt][j][3] + b1;
            }
        }
    }
}

// ============================================================================
// Launch: prep kernels then single fused kernel. No streams, no events.
// ============================================================================
extern "C" void kernel_launch(void* const* d_in, const int* in_sizes, int n_in,
                              void* d_out, int out_size) {
    const float* x    = (const float*)d_in[0];
    const float* ow   = (const float*)d_in[1];
    const float* ob   = (const float*)d_in[2];
    const float* wgt  = (const float*)d_in[3];
    const float* bias = (const float*)d_in[4];
    float* out = (float*)d_out;

    dim3 gn(Hh, BATCH);
    nhwc_kernel<<<gn, 256>>>(x);
    prep_wfrag_kernel<<<(9 * 8 * 16 * 32 + 255) / 256, 256>>>(wgt);
    prep_ofrag_kernel<<<(9 * 8 * 4 * 32 + 255) / 256, 256>>>(ow);

    cudaFuncSetAttribute(fused_dsconv_kernel,
                         cudaFuncAttributeMaxDynamicSharedMemorySize,
                         SMEM_TOTAL_F);
    dim3 gf(HW / MPX, BATCH);
    fused_dsconv_kernel<<<gf, 256, SMEM_TOTAL_F>>>(ob, bias, out);
}